// round 11
// baseline (speedup 1.0000x reference)
#include <cuda_runtime.h>
#include <cuda_fp16.h>
#include <math.h>
#include <stdint.h>

// Problem constants
#define B_    64
#define T_    2048
#define ENC_  512
#define DEC_  1024
#define HID_  256
#define KCONV 31
#define PADC  15

// Tiling: CTA = 128 (bt) x 256 (h), 512 threads, K-chunk 64, double-buffered
// stage (bytes): A[128*144] | W[256*144]   (fp16, 72 elems/row = 64 + 8 pad)
#define A_OFF 0
#define W_OFF 18432
#define ROWB  144
#define STAGE_B 55296
#define ESMEM (2 * STAGE_B)       // 110592

#define NSLICE 32                 // att_c t-slices (64 timesteps each)

// ---------------- device scratch ----------------
__device__ __half g_Wh[HID_ * ENC_];            // W_enc in fp16
__device__ __half g_F[HID_ * 32];               // fused conv filter, col 31 = 0
__device__ float g_dec[B_ * HID_];              // dec projection + b_enc
__device__ float g_energy[B_ * T_];
__device__ float g_part[B_ * NSLICE * ENC_];    // att_c partials

// ---------------- PTX helpers ----------------
__device__ __forceinline__ void cp16(uint32_t dst, const void* src) {
    asm volatile("cp.async.cg.shared.global [%0], [%1], 16;\n" :: "r"(dst), "l"(src));
}
#define CP_COMMIT() asm volatile("cp.async.commit_group;\n" ::: "memory")
#define CP_WAIT0()  asm volatile("cp.async.wait_group 0;\n" ::: "memory")

__device__ __forceinline__ void ldsm_x4(uint32_t (&r)[4], uint32_t addr) {
    asm volatile("ldmatrix.sync.aligned.m8n8.x4.shared.b16 {%0,%1,%2,%3}, [%4];"
                 : "=r"(r[0]), "=r"(r[1]), "=r"(r[2]), "=r"(r[3]) : "r"(addr));
}

__device__ __forceinline__ void mma_f16(float& c0, float& c1, float& c2, float& c3,
                                        uint32_t a0, uint32_t a1, uint32_t a2, uint32_t a3,
                                        uint32_t b0, uint32_t b1) {
    asm volatile(
        "mma.sync.aligned.m16n8k16.row.col.f32.f16.f16.f32 "
        "{%0,%1,%2,%3}, {%4,%5,%6,%7}, {%8,%9}, {%0,%1,%2,%3};"
        : "+f"(c0), "+f"(c1), "+f"(c2), "+f"(c3)
        : "r"(a0), "r"(a1), "r"(a2), "r"(a3), "r"(b0), "r"(b1));
}

__device__ __forceinline__ float fast_tanh(float x) {
    float y;
    asm("tanh.approx.f32 %0, %1;" : "=f"(y) : "f"(x));
    return y;
}

// ---------------- merged prep kernel (R8/R10 parallel scheme) ----------------
__global__ void prep_all(const float* __restrict__ W_enc,
                         const float* __restrict__ W_att,
                         const float* __restrict__ conv_w,
                         const float* __restrict__ dec_state,
                         const float* __restrict__ W_dec,
                         const float* __restrict__ b_enc) {
    int bx = blockIdx.x, tid = threadIdx.x;
    if (bx < 512) {
        int i = bx * 256 + tid;
        g_Wh[i] = __float2half_rn(W_enc[i]);
    } else if (bx < 544) {
        int i = (bx - 512) * 256 + tid;
        int h = i >> 5, k = i & 31;
        float s = 0.f;
        if (k < KCONV) {
            #pragma unroll
            for (int c = 0; c < 32; c++) s += W_att[h * 32 + c] * conv_w[c * KCONV + k];
        }
        g_F[i] = __float2half_rn(s);
    } else {
        int wid_g = (bx - 544) * 8 + (tid >> 5);
        int lane = tid & 31;
        int b = wid_g >> 8, h = wid_g & 255;
        const float4* d = (const float4*)(dec_state + (size_t)b * DEC_);
        const float4* w = (const float4*)(W_dec + (size_t)h * DEC_);
        float s = 0.f;
        #pragma unroll
        for (int it = 0; it < 8; it++) {
            float4 dv = d[lane + it * 32];
            float4 wv = w[lane + it * 32];
            s += dv.x * wv.x + dv.y * wv.y + dv.z * wv.z + dv.w * wv.w;
        }
        #pragma unroll
        for (int off = 16; off > 0; off >>= 1) s += __shfl_xor_sync(0xffffffffu, s, off);
        if (lane == 0) g_dec[wid_g] = s + b_enc[h];
    }
}

// ---------------- energy kernel: single-pass fp16, masked-tile skip ----------------
__global__ void __launch_bounds__(512)
energy_kernel(const float* __restrict__ enc,
              const float* __restrict__ prev,
              const float* __restrict__ w_w,
              const int* __restrict__ text_len) {
    extern __shared__ char sm[];
    uint32_t smb;
    asm("{ .reg .u64 t; cvta.to.shared.u64 t, %1; cvt.u32.u64 %0, t; }"
        : "=r"(smb) : "l"(sm));

    const int tid  = threadIdx.x;
    const int lane = tid & 31;
    const int warp = tid >> 5;
    const int wm   = warp & 3;     // rows [wm*32, +32)
    const int wn   = warp >> 2;    // cols [wn*64, +64)

    const int m0 = blockIdx.x * 128;
    const int b  = m0 >> 11;
    const int t0 = m0 & (T_ - 1);

    // Masked-tile skip: softmax never reads energy at t >= len.
    if (t0 >= text_len[b]) return;

    // producer roles
    const int arow  = tid >> 2;    // 0..127 (A row)
    const int aq    = tid & 3;     // 16-col group
    const int wrow  = tid >> 1;    // 0..255 (W row)
    const int whalf = tid & 1;     // 32-col half

    // ldmatrix lane addressing
    const int g  = lane >> 2, tq = lane & 3;
    const int a_row = (lane & 7) + ((lane >> 3) & 1) * 8;
    const int a_col = ((lane >> 4) & 1) * 8;
    const int b_row = (lane & 7) + ((lane >> 4) & 1) * 8;
    const int b_col = ((lane >> 3) & 1) * 8;

    float acc[2][8][4];
    #pragma unroll
    for (int mi = 0; mi < 2; mi++)
        #pragma unroll
        for (int ni = 0; ni < 8; ni++)
            #pragma unroll
            for (int q = 0; q < 4; q++) acc[mi][ni][q] = 0.f;

    const float* asrc = enc + ((size_t)b * T_ + t0 + arow) * ENC_ + aq * 16;
    const __half* wsrc = g_Wh + (size_t)wrow * ENC_ + whalf * 32;

    float4 av[4];   // A prefetch (16 floats)
    float  pv[8];   // prev prefetch for conv chunk

    auto loadW = [&](int s, int kc) {
        uint32_t dw = smb + s * STAGE_B + W_OFF + wrow * ROWB + whalf * 64;
        #pragma unroll
        for (int j = 0; j < 4; j++) cp16(dw + j * 16, wsrc + kc + j * 8);
    };
    auto loadA = [&](int kc) {
        #pragma unroll
        for (int j = 0; j < 4; j++) av[j] = *(const float4*)(asrc + kc + j * 4);
    };
    auto storeA = [&](int s) {
        uint32_t hv[8];
        #pragma unroll
        for (int j = 0; j < 4; j++) {
            __half2 p0 = __floats2half2_rn(av[j].x, av[j].y);
            __half2 p1 = __floats2half2_rn(av[j].z, av[j].w);
            hv[2*j]   = *(uint32_t*)&p0;
            hv[2*j+1] = *(uint32_t*)&p1;
        }
        char* da = sm + s * STAGE_B + A_OFF + arow * ROWB + aq * 32;
        *(uint4*)(da)      = make_uint4(hv[0], hv[1], hv[2], hv[3]);
        *(uint4*)(da + 16) = make_uint4(hv[4], hv[5], hv[6], hv[7]);
    };
    auto loadF = [&](int s) {
        uint32_t dw = smb + s * STAGE_B + W_OFF + wrow * ROWB + whalf * 32;
        cp16(dw,      g_F + wrow * 32 + whalf * 16);
        cp16(dw + 16, g_F + wrow * 32 + whalf * 16 + 8);
    };
    auto loadPrev = [&]() {
        #pragma unroll
        for (int e = 0; e < 8; e++) {
            int k = aq * 8 + e;
            int t = t0 + arow - PADC + k;
            pv[e] = (k < KCONV && t >= 0 && t < T_) ? prev[b * T_ + t] : 0.f;
        }
    };
    auto storePrev = [&](int s) {
        uint32_t hw[4];
        #pragma unroll
        for (int q = 0; q < 4; q++) {
            __half2 hp = __floats2half2_rn(pv[2*q], pv[2*q+1]);
            hw[q] = *(uint32_t*)&hp;
        }
        *(uint4*)(sm + s * STAGE_B + A_OFF + arow * ROWB + aq * 16)
            = make_uint4(hw[0], hw[1], hw[2], hw[3]);
    };

    auto consume = [&](int s, int ksteps) {
        const uint32_t base = smb + s * STAGE_B;
        for (int ks = 0; ks < ksteps; ks++) {
            const int kb = ks * 16;
            uint32_t af[2][4];
            #pragma unroll
            for (int mi = 0; mi < 2; mi++)
                ldsm_x4(af[mi], base + A_OFF + (wm * 32 + mi * 16 + a_row) * ROWB
                                + (kb + a_col) * 2);
            #pragma unroll
            for (int p = 0; p < 4; p++) {
                uint32_t wf[4];
                ldsm_x4(wf, base + W_OFF + (wn * 64 + p * 16 + b_row) * ROWB
                            + (kb + b_col) * 2);
                #pragma unroll
                for (int mi = 0; mi < 2; mi++) {
                    mma_f16(acc[mi][2*p][0], acc[mi][2*p][1], acc[mi][2*p][2], acc[mi][2*p][3],
                            af[mi][0], af[mi][1], af[mi][2], af[mi][3], wf[0], wf[1]);
                    mma_f16(acc[mi][2*p+1][0], acc[mi][2*p+1][1], acc[mi][2*p+1][2], acc[mi][2*p+1][3],
                            af[mi][0], af[mi][1], af[mi][2], af[mi][3], wf[2], wf[3]);
                }
            }
        }
    };

    // ---- prologue: chunk 0 ----
    loadW(0, 0);
    CP_COMMIT();
    loadA(0);
    storeA(0);
    CP_WAIT0();
    __syncthreads();

    // ---- main loop: chunks 0..7 = GEMM, chunk 8 = conv ----
    for (int c = 0; c <= 8; c++) {
        const int cur = c & 1, nxt = cur ^ 1;
        if (c < 7) {
            loadW(nxt, (c + 1) * 64);
            CP_COMMIT();
            loadA((c + 1) * 64);
        } else if (c == 7) {
            loadF(nxt);
            CP_COMMIT();
            loadPrev();
        }
        if (c < 8) consume(cur, 4);
        else       consume(cur, 2);
        if (c < 7) {
            storeA(nxt);
            CP_WAIT0();
        } else if (c == 7) {
            storePrev(nxt);
            CP_WAIT0();
        }
        __syncthreads();
    }

    // ---- epilogue: energy[row] = sum_h w_w[h]*tanh(acc + dec) ----
    float* red = (float*)sm;   // 128 x 4 floats (aliases stage0, post-sync)
    float wv[16], dv[16];
    {
        int cbase = wn * 64 + tq * 2;
        #pragma unroll
        for (int ni = 0; ni < 8; ni++) {
            int n = cbase + ni * 8;
            wv[2 * ni]     = w_w[n];
            wv[2 * ni + 1] = w_w[n + 1];
            dv[2 * ni]     = g_dec[b * HID_ + n];
            dv[2 * ni + 1] = g_dec[b * HID_ + n + 1];
        }
    }
    #pragma unroll
    for (int mi = 0; mi < 2; mi++) {
        #pragma unroll
        for (int h2 = 0; h2 < 2; h2++) {
            float p = 0.f;
            #pragma unroll
            for (int ni = 0; ni < 8; ni++) {
                #pragma unroll
                for (int j = 0; j < 2; j++) {
                    float s = acc[mi][ni][h2 * 2 + j] + dv[2 * ni + j];
                    p += wv[2 * ni + j] * fast_tanh(s);
                }
            }
            p += __shfl_xor_sync(0xffffffffu, p, 1);
            p += __shfl_xor_sync(0xffffffffu, p, 2);
            if (tq == 0) {
                int row = wm * 32 + mi * 16 + h2 * 8 + g;
                red[row * 4 + wn] = p;
            }
        }
    }
    __syncthreads();
    if (tid < 128) {
        g_energy[m0 + tid] = red[tid * 4] + red[tid * 4 + 1]
                           + red[tid * 4 + 2] + red[tid * 4 + 3];
    }
}

// ---------------- masked softmax over T ----------------
__global__ void softmax_kernel(const int* __restrict__ text_len, float* __restrict__ out) {
    __shared__ float sh[T_];
    __shared__ float rbuf[256];
    int b = blockIdx.x, tid = threadIdx.x;
    int len = text_len[b];

    float mx = -INFINITY;
    for (int t = tid; t < T_; t += 256) {
        float v = (t < len) ? g_energy[b * T_ + t] : -INFINITY;
        sh[t] = v;
        mx = fmaxf(mx, v);
    }
    rbuf[tid] = mx; __syncthreads();
    for (int s = 128; s > 0; s >>= 1) {
        if (tid < s) rbuf[tid] = fmaxf(rbuf[tid], rbuf[tid + s]);
        __syncthreads();
    }
    mx = rbuf[0];
    __syncthreads();

    float sum = 0.f;
    for (int t = tid; t < T_; t += 256) {
        float v = sh[t];
        float e = (v == -INFINITY) ? 0.f : expf(v - mx);
        sh[t] = e;
        sum += e;
    }
    rbuf[tid] = sum; __syncthreads();
    for (int s = 128; s > 0; s >>= 1) {
        if (tid < s) rbuf[tid] += rbuf[tid + s];
        __syncthreads();
    }
    float inv = 1.f / rbuf[0];

    float* attw = out + B_ * ENC_;
    for (int t = tid; t < T_; t += 256)
        attw[b * T_ + t] = sh[t] * inv;
}

// ---------------- att_c partials: 32 t-slices of 64, masked skip ----------------
__global__ void attc_part(const float* __restrict__ enc, const float* __restrict__ attw,
                          const int* __restrict__ text_len) {
    __shared__ float w[64];
    int ts = blockIdx.x;    // 0..31
    int b  = blockIdx.y;
    int tid = threadIdx.x;  // 128

    // Slices fully beyond text_len have zero attention weight: skip the enc read.
    if (ts * 64 >= text_len[b]) {
        float4 z = make_float4(0.f, 0.f, 0.f, 0.f);
        *(float4*)&g_part[((b * NSLICE + ts) * ENC_) + tid * 4] = z;
        return;
    }

    if (tid < 64) w[tid] = attw[b * T_ + ts * 64 + tid];
    __syncthreads();

    const float4* e4 = (const float4*)(enc + ((size_t)b * T_ + ts * 64) * ENC_) + tid;
    float ax = 0.f, ay = 0.f, az = 0.f, aw = 0.f;
    #pragma unroll 8
    for (int tt = 0; tt < 64; tt++) {
        float4 v = e4[(size_t)tt * (ENC_ / 4)];
        float ww = w[tt];
        ax += ww * v.x; ay += ww * v.y; az += ww * v.z; aw += ww * v.w;
    }
    float4 rr; rr.x = ax; rr.y = ay; rr.z = az; rr.w = aw;
    *(float4*)&g_part[((b * NSLICE + ts) * ENC_) + tid * 4] = rr;
}

__global__ void attc_reduce(float* __restrict__ out) {
    int i = blockIdx.x * 256 + threadIdx.x;
    if (i < B_ * ENC_) {
        int b = i >> 9, c = i & (ENC_ - 1);
        float s = 0.f;
        #pragma unroll
        for (int ts = 0; ts < NSLICE; ts++) s += g_part[(b * NSLICE + ts) * ENC_ + c];
        out[i] = s;
    }
}

// ---------------- launch ----------------
extern "C" void kernel_launch(void* const* d_in, const int* in_sizes, int n_in,
                              void* d_out, int out_size) {
    const float* enc       = (const float*)d_in[0];
    const float* dec_state = (const float*)d_in[1];
    const float* prev      = (const float*)d_in[2];
    const int*   text_len  = (const int*)d_in[3];
    const float* W_enc     = (const float*)d_in[4];
    const float* b_enc     = (const float*)d_in[5];
    const float* W_dec     = (const float*)d_in[6];
    const float* W_att     = (const float*)d_in[7];
    const float* conv_w    = (const float*)d_in[8];
    const float* w_w       = (const float*)d_in[9];
    // d_in[10] = w_b: additive constant cancels in softmax.
    float* out = (float*)d_out;

    cudaFuncSetAttribute(energy_kernel, cudaFuncAttributeMaxDynamicSharedMemorySize, ESMEM);

    prep_all<<<2592, 256>>>(W_enc, W_att, conv_w, dec_state, W_dec, b_enc);

    energy_kernel<<<B_ * T_ / 128, 512, ESMEM>>>(enc, prev, w_w, text_len);

    softmax_kernel<<<B_, 256>>>(text_len, out);

    attc_part<<<dim3(NSLICE, B_), 128>>>(enc, out + B_ * ENC_, text_len);
    attc_reduce<<<(B_ * ENC_ + 255) / 256, 256>>>(out);
}

// round 14
// speedup vs baseline: 1.3555x; 1.3555x over previous
#include <cuda_runtime.h>
#include <cuda_fp16.h>
#include <math.h>
#include <stdint.h>

// Problem constants
#define B_    64
#define T_    2048
#define ENC_  512
#define DEC_  1024
#define HID_  256
#define KCONV 31
#define PADC  15

// Tiling: CTA = 128 (bt) x 256 (h), 512 threads, K-chunk 64, double-buffered
// stage (bytes): A[128*144] | W[256*144]   (fp16, 72 elems/row = 64 + 8 pad)
#define A_OFF 0
#define W_OFF 18432
#define ROWB  144
#define STAGE_B 55296
#define ESMEM (2 * STAGE_B)       // 110592

#define NSLICE 32                 // att_c t-slices (64 timesteps each)

// ---------------- device scratch ----------------
__device__ __half g_Wh[HID_ * ENC_];            // W_enc in fp16
__device__ __half g_F[HID_ * 32];               // fused conv filter, col 31 = 0
__device__ float g_dec[B_ * HID_];              // dec projection + b_enc
__device__ float g_energy[B_ * T_];
__device__ float g_part[B_ * NSLICE * ENC_];    // att_c partials

// ---------------- PTX helpers ----------------
__device__ __forceinline__ void cp16(uint32_t dst, const void* src) {
    asm volatile("cp.async.cg.shared.global [%0], [%1], 16;\n" :: "r"(dst), "l"(src));
}
#define CP_COMMIT() asm volatile("cp.async.commit_group;\n" ::: "memory")
#define CP_WAIT0()  asm volatile("cp.async.wait_group 0;\n" ::: "memory")

__device__ __forceinline__ void ldsm_x4(uint32_t (&r)[4], uint32_t addr) {
    asm volatile("ldmatrix.sync.aligned.m8n8.x4.shared.b16 {%0,%1,%2,%3}, [%4];"
                 : "=r"(r[0]), "=r"(r[1]), "=r"(r[2]), "=r"(r[3]) : "r"(addr));
}

__device__ __forceinline__ void mma_f16(float& c0, float& c1, float& c2, float& c3,
                                        uint32_t a0, uint32_t a1, uint32_t a2, uint32_t a3,
                                        uint32_t b0, uint32_t b1) {
    asm volatile(
        "mma.sync.aligned.m16n8k16.row.col.f32.f16.f16.f32 "
        "{%0,%1,%2,%3}, {%4,%5,%6,%7}, {%8,%9}, {%0,%1,%2,%3};"
        : "+f"(c0), "+f"(c1), "+f"(c2), "+f"(c3)
        : "r"(a0), "r"(a1), "r"(a2), "r"(a3), "r"(b0), "r"(b1));
}

// ---------------- merged prep kernel (R8/R10 parallel scheme) ----------------
__global__ void prep_all(const float* __restrict__ W_enc,
                         const float* __restrict__ W_att,
                         const float* __restrict__ conv_w,
                         const float* __restrict__ dec_state,
                         const float* __restrict__ W_dec,
                         const float* __restrict__ b_enc) {
    int bx = blockIdx.x, tid = threadIdx.x;
    if (bx < 512) {
        int i = bx * 256 + tid;
        g_Wh[i] = __float2half_rn(W_enc[i]);
    } else if (bx < 544) {
        int i = (bx - 512) * 256 + tid;
        int h = i >> 5, k = i & 31;
        float s = 0.f;
        if (k < KCONV) {
            #pragma unroll
            for (int c = 0; c < 32; c++) s += W_att[h * 32 + c] * conv_w[c * KCONV + k];
        }
        g_F[i] = __float2half_rn(s);
    } else {
        int wid_g = (bx - 544) * 8 + (tid >> 5);
        int lane = tid & 31;
        int b = wid_g >> 8, h = wid_g & 255;
        const float4* d = (const float4*)(dec_state + (size_t)b * DEC_);
        const float4* w = (const float4*)(W_dec + (size_t)h * DEC_);
        float s = 0.f;
        #pragma unroll
        for (int it = 0; it < 8; it++) {
            float4 dv = d[lane + it * 32];
            float4 wv = w[lane + it * 32];
            s += dv.x * wv.x + dv.y * wv.y + dv.z * wv.z + dv.w * wv.w;
        }
        #pragma unroll
        for (int off = 16; off > 0; off >>= 1) s += __shfl_xor_sync(0xffffffffu, s, off);
        if (lane == 0) g_dec[wid_g] = s + b_enc[h];
    }
}

// ---------------- energy kernel: single-pass fp16, masked-tile skip ----------------
__global__ void __launch_bounds__(512)
energy_kernel(const float* __restrict__ enc,
              const float* __restrict__ prev,
              const float* __restrict__ w_w,
              const int* __restrict__ text_len) {
    extern __shared__ char sm[];
    uint32_t smb;
    asm("{ .reg .u64 t; cvta.to.shared.u64 t, %1; cvt.u32.u64 %0, t; }"
        : "=r"(smb) : "l"(sm));

    const int tid  = threadIdx.x;
    const int lane = tid & 31;
    const int warp = tid >> 5;
    const int wm   = warp & 3;     // rows [wm*32, +32)
    const int wn   = warp >> 2;    // cols [wn*64, +64)

    const int m0 = blockIdx.x * 128;
    const int b  = m0 >> 11;
    const int t0 = m0 & (T_ - 1);

    // Masked-tile skip: softmax never reads energy at t >= len.
    if (t0 >= text_len[b]) return;

    // producer roles
    const int arow  = tid >> 2;    // 0..127 (A row)
    const int aq    = tid & 3;     // 16-col group
    const int wrow  = tid >> 1;    // 0..255 (W row)
    const int whalf = tid & 1;     // 32-col half

    // ldmatrix lane addressing
    const int g  = lane >> 2, tq = lane & 3;
    const int a_row = (lane & 7) + ((lane >> 3) & 1) * 8;
    const int a_col = ((lane >> 4) & 1) * 8;
    const int b_row = (lane & 7) + ((lane >> 4) & 1) * 8;
    const int b_col = ((lane >> 3) & 1) * 8;

    float acc[2][8][4];
    #pragma unroll
    for (int mi = 0; mi < 2; mi++)
        #pragma unroll
        for (int ni = 0; ni < 8; ni++)
            #pragma unroll
            for (int q = 0; q < 4; q++) acc[mi][ni][q] = 0.f;

    const float* asrc = enc + ((size_t)b * T_ + t0 + arow) * ENC_ + aq * 16;
    const __half* wsrc = g_Wh + (size_t)wrow * ENC_ + whalf * 32;

    float4 av[4];   // A prefetch (16 floats)
    float  pv[8];   // prev prefetch for conv chunk

    auto loadW = [&](int s, int kc) {
        uint32_t dw = smb + s * STAGE_B + W_OFF + wrow * ROWB + whalf * 64;
        #pragma unroll
        for (int j = 0; j < 4; j++) cp16(dw + j * 16, wsrc + kc + j * 8);
    };
    auto loadA = [&](int kc) {
        #pragma unroll
        for (int j = 0; j < 4; j++) av[j] = *(const float4*)(asrc + kc + j * 4);
    };
    auto storeA = [&](int s) {
        uint32_t hv[8];
        #pragma unroll
        for (int j = 0; j < 4; j++) {
            __half2 p0 = __floats2half2_rn(av[j].x, av[j].y);
            __half2 p1 = __floats2half2_rn(av[j].z, av[j].w);
            hv[2*j]   = *(uint32_t*)&p0;
            hv[2*j+1] = *(uint32_t*)&p1;
        }
        char* da = sm + s * STAGE_B + A_OFF + arow * ROWB + aq * 32;
        *(uint4*)(da)      = make_uint4(hv[0], hv[1], hv[2], hv[3]);
        *(uint4*)(da + 16) = make_uint4(hv[4], hv[5], hv[6], hv[7]);
    };
    auto loadF = [&](int s) {
        uint32_t dw = smb + s * STAGE_B + W_OFF + wrow * ROWB + whalf * 32;
        cp16(dw,      g_F + wrow * 32 + whalf * 16);
        cp16(dw + 16, g_F + wrow * 32 + whalf * 16 + 8);
    };
    auto loadPrev = [&]() {
        #pragma unroll
        for (int e = 0; e < 8; e++) {
            int k = aq * 8 + e;
            int t = t0 + arow - PADC + k;
            pv[e] = (k < KCONV && t >= 0 && t < T_) ? prev[b * T_ + t] : 0.f;
        }
    };
    auto storePrev = [&](int s) {
        uint32_t hw[4];
        #pragma unroll
        for (int q = 0; q < 4; q++) {
            __half2 hp = __floats2half2_rn(pv[2*q], pv[2*q+1]);
            hw[q] = *(uint32_t*)&hp;
        }
        *(uint4*)(sm + s * STAGE_B + A_OFF + arow * ROWB + aq * 16)
            = make_uint4(hw[0], hw[1], hw[2], hw[3]);
    };

    auto consume = [&](int s, int ksteps) {
        const uint32_t base = smb + s * STAGE_B;
        for (int ks = 0; ks < ksteps; ks++) {
            const int kb = ks * 16;
            uint32_t af[2][4];
            #pragma unroll
            for (int mi = 0; mi < 2; mi++)
                ldsm_x4(af[mi], base + A_OFF + (wm * 32 + mi * 16 + a_row) * ROWB
                                + (kb + a_col) * 2);
            #pragma unroll
            for (int p = 0; p < 4; p++) {
                uint32_t wf[4];
                ldsm_x4(wf, base + W_OFF + (wn * 64 + p * 16 + b_row) * ROWB
                            + (kb + b_col) * 2);
                #pragma unroll
                for (int mi = 0; mi < 2; mi++) {
                    mma_f16(acc[mi][2*p][0], acc[mi][2*p][1], acc[mi][2*p][2], acc[mi][2*p][3],
                            af[mi][0], af[mi][1], af[mi][2], af[mi][3], wf[0], wf[1]);
                    mma_f16(acc[mi][2*p+1][0], acc[mi][2*p+1][1], acc[mi][2*p+1][2], acc[mi][2*p+1][3],
                            af[mi][0], af[mi][1], af[mi][2], af[mi][3], wf[2], wf[3]);
                }
            }
        }
    };

    // ---- prologue: chunk 0 ----
    loadW(0, 0);
    CP_COMMIT();
    loadA(0);
    storeA(0);
    CP_WAIT0();
    __syncthreads();

    // ---- main loop: chunks 0..7 = GEMM, chunk 8 = conv ----
    for (int c = 0; c <= 8; c++) {
        const int cur = c & 1, nxt = cur ^ 1;
        if (c < 7) {
            loadW(nxt, (c + 1) * 64);
            CP_COMMIT();
            loadA((c + 1) * 64);
        } else if (c == 7) {
            loadF(nxt);
            CP_COMMIT();
            loadPrev();
        }
        if (c < 8) consume(cur, 4);
        else       consume(cur, 2);
        if (c < 7) {
            storeA(nxt);
            CP_WAIT0();
        } else if (c == 7) {
            storePrev(nxt);
            CP_WAIT0();
        }
        __syncthreads();
    }

    // ---- epilogue: energy[row] = sum_h w_w[h]*tanh(acc + dec) ----
    float* red = (float*)sm;   // 128 x 4 floats (aliases stage0, post-sync)
    float wv[16], dv[16];
    {
        int cbase = wn * 64 + tq * 2;
        #pragma unroll
        for (int ni = 0; ni < 8; ni++) {
            int n = cbase + ni * 8;
            wv[2 * ni]     = w_w[n];
            wv[2 * ni + 1] = w_w[n + 1];
            dv[2 * ni]     = g_dec[b * HID_ + n];
            dv[2 * ni + 1] = g_dec[b * HID_ + n + 1];
        }
    }
    #pragma unroll
    for (int mi = 0; mi < 2; mi++) {
        #pragma unroll
        for (int h2 = 0; h2 < 2; h2++) {
            float p = 0.f;
            #pragma unroll
            for (int ni = 0; ni < 8; ni++) {
                #pragma unroll
                for (int j = 0; j < 2; j++) {
                    float s = acc[mi][ni][h2 * 2 + j] + dv[2 * ni + j];
                    p += wv[2 * ni + j] * tanhf(s);
                }
            }
            p += __shfl_xor_sync(0xffffffffu, p, 1);
            p += __shfl_xor_sync(0xffffffffu, p, 2);
            if (tq == 0) {
                int row = wm * 32 + mi * 16 + h2 * 8 + g;
                red[row * 4 + wn] = p;
            }
        }
    }
    __syncthreads();
    if (tid < 128) {
        g_energy[m0 + tid] = red[tid * 4] + red[tid * 4 + 1]
                           + red[tid * 4 + 2] + red[tid * 4 + 3];
    }
}

// ---------------- masked softmax over T (loops bounded by len) ----------------
__global__ void softmax_kernel(const int* __restrict__ text_len, float* __restrict__ out) {
    __shared__ float sh[T_];
    __shared__ float rbuf[256];
    int b = blockIdx.x, tid = threadIdx.x;
    int len = text_len[b];

    float mx = -INFINITY;
    for (int t = tid; t < len; t += 256) {
        float v = g_energy[b * T_ + t];
        sh[t] = v;
        mx = fmaxf(mx, v);
    }
    rbuf[tid] = mx; __syncthreads();
    for (int s = 128; s > 0; s >>= 1) {
        if (tid < s) rbuf[tid] = fmaxf(rbuf[tid], rbuf[tid + s]);
        __syncthreads();
    }
    mx = rbuf[0];
    __syncthreads();

    float sum = 0.f;
    for (int t = tid; t < len; t += 256) {
        float e = __expf(sh[t] - mx);
        sh[t] = e;
        sum += e;
    }
    rbuf[tid] = sum; __syncthreads();
    for (int s = 128; s > 0; s >>= 1) {
        if (tid < s) rbuf[tid] += rbuf[tid + s];
        __syncthreads();
    }
    float inv = 1.f / rbuf[0];

    float* attw = out + B_ * ENC_;
    for (int t = tid; t < len; t += 256)
        attw[b * T_ + t] = sh[t] * inv;
    for (int t = len + tid - (len & 255) + ((tid >= (len & 255)) ? 0 : 256);
         t < T_; t += 256)
        attw[b * T_ + t] = 0.f;
}

// ---------------- att_c partials: 32 t-slices of 64, masked skip ----------------
__global__ void attc_part(const float* __restrict__ enc, const float* __restrict__ attw,
                          const int* __restrict__ text_len) {
    __shared__ float w[64];
    int ts = blockIdx.x;    // 0..31
    int b  = blockIdx.y;
    int tid = threadIdx.x;  // 128

    // Slices fully beyond text_len have zero attention weight: skip the enc read.
    if (ts * 64 >= text_len[b]) {
        float4 z = make_float4(0.f, 0.f, 0.f, 0.f);
        *(float4*)&g_part[((b * NSLICE + ts) * ENC_) + tid * 4] = z;
        return;
    }

    if (tid < 64) w[tid] = attw[b * T_ + ts * 64 + tid];
    __syncthreads();

    const float4* e4 = (const float4*)(enc + ((size_t)b * T_ + ts * 64) * ENC_) + tid;
    float ax = 0.f, ay = 0.f, az = 0.f, aw = 0.f;
    #pragma unroll 8
    for (int tt = 0; tt < 64; tt++) {
        float4 v = e4[(size_t)tt * (ENC_ / 4)];
        float ww = w[tt];
        ax += ww * v.x; ay += ww * v.y; az += ww * v.z; aw += ww * v.w;
    }
    float4 rr; rr.x = ax; rr.y = ay; rr.z = az; rr.w = aw;
    *(float4*)&g_part[((b * NSLICE + ts) * ENC_) + tid * 4] = rr;
}

__global__ void attc_reduce(float* __restrict__ out) {
    int i = blockIdx.x * 256 + threadIdx.x;
    if (i < B_ * ENC_) {
        int b = i >> 9, c = i & (ENC_ - 1);
        float s = 0.f;
        #pragma unroll
        for (int ts = 0; ts < NSLICE; ts++) s += g_part[(b * NSLICE + ts) * ENC_ + c];
        out[i] = s;
    }
}

// ---------------- launch ----------------
extern "C" void kernel_launch(void* const* d_in, const int* in_sizes, int n_in,
                              void* d_out, int out_size) {
    const float* enc       = (const float*)d_in[0];
    const float* dec_state = (const float*)d_in[1];
    const float* prev      = (const float*)d_in[2];
    const int*   text_len  = (const int*)d_in[3];
    const float* W_enc     = (const float*)d_in[4];
    const float* b_enc     = (const float*)d_in[5];
    const float* W_dec     = (const float*)d_in[6];
    const float* W_att     = (const float*)d_in[7];
    const float* conv_w    = (const float*)d_in[8];
    const float* w_w       = (const float*)d_in[9];
    // d_in[10] = w_b: additive constant cancels in softmax.
    float* out = (float*)d_out;

    cudaFuncSetAttribute(energy_kernel, cudaFuncAttributeMaxDynamicSharedMemorySize, ESMEM);

    prep_all<<<2592, 256>>>(W_enc, W_att, conv_w, dec_state, W_dec, b_enc);

    energy_kernel<<<B_ * T_ / 128, 512, ESMEM>>>(enc, prev, w_w, text_len);

    softmax_kernel<<<B_, 256>>>(text_len, out);

    attc_part<<<dim3(NSLICE, B_), 128>>>(enc, out + B_ * ENC_, text_len);
    attc_reduce<<<(B_ * ENC_ + 255) / 256, 256>>>(out);
}

// round 16
// speedup vs baseline: 1.3815x; 1.0192x over previous
#include <cuda_runtime.h>
#include <cuda_fp16.h>
#include <math.h>
#include <stdint.h>

// Problem constants
#define B_    64
#define T_    2048
#define ENC_  512
#define DEC_  1024
#define HID_  256
#define KCONV 31
#define PADC  15

// Tiling: CTA = 128 (bt) x 256 (h), 512 threads, K-chunk 64, double-buffered
// stage (bytes): A[128*144] | W[256*144]   (fp16, 72 elems/row = 64 + 8 pad)
#define A_OFF 0
#define W_OFF 18432
#define ROWB  144
#define STAGE_B 55296
#define ESMEM (2 * STAGE_B)       // 110592

#define NSLICE 32                 // att_c t-slices (64 timesteps each)

// ---------------- device scratch ----------------
__device__ __half g_Wh[HID_ * ENC_];            // W_enc in fp16
__device__ __half g_F[HID_ * 32];               // fused conv filter, col 31 = 0
__device__ float g_dec[B_ * HID_];              // dec projection + b_enc
__device__ float g_energy[B_ * T_];

// ---------------- PTX helpers ----------------
__device__ __forceinline__ void cp16(uint32_t dst, const void* src) {
    asm volatile("cp.async.cg.shared.global [%0], [%1], 16;\n" :: "r"(dst), "l"(src));
}
#define CP_COMMIT() asm volatile("cp.async.commit_group;\n" ::: "memory")
#define CP_WAIT0()  asm volatile("cp.async.wait_group 0;\n" ::: "memory")

__device__ __forceinline__ void ldsm_x4(uint32_t (&r)[4], uint32_t addr) {
    asm volatile("ldmatrix.sync.aligned.m8n8.x4.shared.b16 {%0,%1,%2,%3}, [%4];"
                 : "=r"(r[0]), "=r"(r[1]), "=r"(r[2]), "=r"(r[3]) : "r"(addr));
}

__device__ __forceinline__ void mma_f16(float& c0, float& c1, float& c2, float& c3,
                                        uint32_t a0, uint32_t a1, uint32_t a2, uint32_t a3,
                                        uint32_t b0, uint32_t b1) {
    asm volatile(
        "mma.sync.aligned.m16n8k16.row.col.f32.f16.f16.f32 "
        "{%0,%1,%2,%3}, {%4,%5,%6,%7}, {%8,%9}, {%0,%1,%2,%3};"
        : "+f"(c0), "+f"(c1), "+f"(c2), "+f"(c3)
        : "r"(a0), "r"(a1), "r"(a2), "r"(a3), "r"(b0), "r"(b1));
}

// ---------------- merged prep kernel ----------------
// blocks [0,512):   W_enc -> fp16
// blocks [512,544): fused conv filter F
// blocks [544,800): dec projection, tiled 8h x 8b per block (W_dec read 8x total)
__global__ void prep_all(const float* __restrict__ W_enc,
                         const float* __restrict__ W_att,
                         const float* __restrict__ conv_w,
                         const float* __restrict__ dec_state,
                         const float* __restrict__ W_dec,
                         const float* __restrict__ b_enc) {
    __shared__ float4 smDec[8][DEC_ / 4];   // 32 KB (dec branch only)
    int bx = blockIdx.x, tid = threadIdx.x;
    if (bx < 512) {
        int i = bx * 256 + tid;
        g_Wh[i] = __float2half_rn(W_enc[i]);
    } else if (bx < 544) {
        int i = (bx - 512) * 256 + tid;
        int h = i >> 5, k = i & 31;
        float s = 0.f;
        if (k < KCONV) {
            #pragma unroll
            for (int c = 0; c < 32; c++) s += W_att[h * 32 + c] * conv_w[c * KCONV + k];
        }
        g_F[i] = __float2half_rn(s);
    } else {
        int idx = bx - 544;          // 0..255
        int hg  = idx & 31;          // h-group (8 h each)
        int bt  = idx >> 5;          // b-tile  (8 b each)
        int wrp = tid >> 5;          // warp -> local h
        int lane = tid & 31;

        // load dec_state tile (8 b x 1024 f32) into smem
        const float4* dsrc = (const float4*)(dec_state + (size_t)(bt * 8) * DEC_);
        #pragma unroll
        for (int j = 0; j < 8; j++) {
            int i4 = j * 256 + tid;
            smDec[i4 >> 8][i4 & 255] = dsrc[i4];
        }
        __syncthreads();

        int h = hg * 8 + wrp;
        const float4* wsrc = (const float4*)(W_dec + (size_t)h * DEC_);
        float acc[8];
        #pragma unroll
        for (int bb = 0; bb < 8; bb++) acc[bb] = 0.f;
        #pragma unroll
        for (int k = 0; k < 8; k++) {
            float4 wv = wsrc[lane + k * 32];
            #pragma unroll
            for (int bb = 0; bb < 8; bb++) {
                float4 dv = smDec[bb][lane + k * 32];
                acc[bb] += dv.x * wv.x + dv.y * wv.y + dv.z * wv.z + dv.w * wv.w;
            }
        }
        #pragma unroll
        for (int bb = 0; bb < 8; bb++) {
            float s = acc[bb];
            #pragma unroll
            for (int off = 16; off > 0; off >>= 1)
                s += __shfl_xor_sync(0xffffffffu, s, off);
            if (lane == 0) g_dec[(bt * 8 + bb) * HID_ + h] = s + b_enc[h];
        }
    }
}

// ---------------- energy kernel: single-pass fp16, masked-tile skip ----------------
__global__ void __launch_bounds__(512)
energy_kernel(const float* __restrict__ enc,
              const float* __restrict__ prev,
              const float* __restrict__ w_w,
              const int* __restrict__ text_len) {
    extern __shared__ char sm[];
    uint32_t smb;
    asm("{ .reg .u64 t; cvta.to.shared.u64 t, %1; cvt.u32.u64 %0, t; }"
        : "=r"(smb) : "l"(sm));

    const int tid  = threadIdx.x;
    const int lane = tid & 31;
    const int warp = tid >> 5;
    const int wm   = warp & 3;     // rows [wm*32, +32)
    const int wn   = warp >> 2;    // cols [wn*64, +64)

    const int m0 = blockIdx.x * 128;
    const int b  = m0 >> 11;
    const int t0 = m0 & (T_ - 1);

    // Masked-tile skip: softmax never reads energy at t >= len.
    if (t0 >= text_len[b]) return;

    // producer roles
    const int arow  = tid >> 2;    // 0..127 (A row)
    const int aq    = tid & 3;     // 16-col group
    const int wrow  = tid >> 1;    // 0..255 (W row)
    const int whalf = tid & 1;     // 32-col half

    // ldmatrix lane addressing
    const int g  = lane >> 2, tq = lane & 3;
    const int a_row = (lane & 7) + ((lane >> 3) & 1) * 8;
    const int a_col = ((lane >> 4) & 1) * 8;
    const int b_row = (lane & 7) + ((lane >> 4) & 1) * 8;
    const int b_col = ((lane >> 3) & 1) * 8;

    float acc[2][8][4];
    #pragma unroll
    for (int mi = 0; mi < 2; mi++)
        #pragma unroll
        for (int ni = 0; ni < 8; ni++)
            #pragma unroll
            for (int q = 0; q < 4; q++) acc[mi][ni][q] = 0.f;

    const float* asrc = enc + ((size_t)b * T_ + t0 + arow) * ENC_ + aq * 16;
    const __half* wsrc = g_Wh + (size_t)wrow * ENC_ + whalf * 32;

    float4 av[4];   // A prefetch (16 floats)
    float  pv[8];   // prev prefetch for conv chunk

    auto loadW = [&](int s, int kc) {
        uint32_t dw = smb + s * STAGE_B + W_OFF + wrow * ROWB + whalf * 64;
        #pragma unroll
        for (int j = 0; j < 4; j++) cp16(dw + j * 16, wsrc + kc + j * 8);
    };
    auto loadA = [&](int kc) {
        #pragma unroll
        for (int j = 0; j < 4; j++) av[j] = *(const float4*)(asrc + kc + j * 4);
    };
    auto storeA = [&](int s) {
        uint32_t hv[8];
        #pragma unroll
        for (int j = 0; j < 4; j++) {
            __half2 p0 = __floats2half2_rn(av[j].x, av[j].y);
            __half2 p1 = __floats2half2_rn(av[j].z, av[j].w);
            hv[2*j]   = *(uint32_t*)&p0;
            hv[2*j+1] = *(uint32_t*)&p1;
        }
        char* da = sm + s * STAGE_B + A_OFF + arow * ROWB + aq * 32;
        *(uint4*)(da)      = make_uint4(hv[0], hv[1], hv[2], hv[3]);
        *(uint4*)(da + 16) = make_uint4(hv[4], hv[5], hv[6], hv[7]);
    };
    auto loadF = [&](int s) {
        uint32_t dw = smb + s * STAGE_B + W_OFF + wrow * ROWB + whalf * 32;
        cp16(dw,      g_F + wrow * 32 + whalf * 16);
        cp16(dw + 16, g_F + wrow * 32 + whalf * 16 + 8);
    };
    auto loadPrev = [&]() {
        #pragma unroll
        for (int e = 0; e < 8; e++) {
            int k = aq * 8 + e;
            int t = t0 + arow - PADC + k;
            pv[e] = (k < KCONV && t >= 0 && t < T_) ? prev[b * T_ + t] : 0.f;
        }
    };
    auto storePrev = [&](int s) {
        uint32_t hw[4];
        #pragma unroll
        for (int q = 0; q < 4; q++) {
            __half2 hp = __floats2half2_rn(pv[2*q], pv[2*q+1]);
            hw[q] = *(uint32_t*)&hp;
        }
        *(uint4*)(sm + s * STAGE_B + A_OFF + arow * ROWB + aq * 16)
            = make_uint4(hw[0], hw[1], hw[2], hw[3]);
    };

    auto consume = [&](int s, int ksteps) {
        const uint32_t base = smb + s * STAGE_B;
        for (int ks = 0; ks < ksteps; ks++) {
            const int kb = ks * 16;
            uint32_t af[2][4];
            #pragma unroll
            for (int mi = 0; mi < 2; mi++)
                ldsm_x4(af[mi], base + A_OFF + (wm * 32 + mi * 16 + a_row) * ROWB
                                + (kb + a_col) * 2);
            #pragma unroll
            for (int p = 0; p < 4; p++) {
                uint32_t wf[4];
                ldsm_x4(wf, base + W_OFF + (wn * 64 + p * 16 + b_row) * ROWB
                            + (kb + b_col) * 2);
                #pragma unroll
                for (int mi = 0; mi < 2; mi++) {
                    mma_f16(acc[mi][2*p][0], acc[mi][2*p][1], acc[mi][2*p][2], acc[mi][2*p][3],
                            af[mi][0], af[mi][1], af[mi][2], af[mi][3], wf[0], wf[1]);
                    mma_f16(acc[mi][2*p+1][0], acc[mi][2*p+1][1], acc[mi][2*p+1][2], acc[mi][2*p+1][3],
                            af[mi][0], af[mi][1], af[mi][2], af[mi][3], wf[2], wf[3]);
                }
            }
        }
    };

    // ---- prologue: chunk 0 ----
    loadW(0, 0);
    CP_COMMIT();
    loadA(0);
    storeA(0);
    CP_WAIT0();
    __syncthreads();

    // ---- main loop: chunks 0..7 = GEMM, chunk 8 = conv ----
    for (int c = 0; c <= 8; c++) {
        const int cur = c & 1, nxt = cur ^ 1;
        if (c < 7) {
            loadW(nxt, (c + 1) * 64);
            CP_COMMIT();
            loadA((c + 1) * 64);
        } else if (c == 7) {
            loadF(nxt);
            CP_COMMIT();
            loadPrev();
        }
        if (c < 8) consume(cur, 4);
        else       consume(cur, 2);
        if (c < 7) {
            storeA(nxt);
            CP_WAIT0();
        } else if (c == 7) {
            storePrev(nxt);
            CP_WAIT0();
        }
        __syncthreads();
    }

    // ---- epilogue: energy[row] = sum_h w_w[h]*tanh(acc + dec) ----
    float* red = (float*)sm;   // 128 x 4 floats (aliases stage0, post-sync)
    float wv[16], dv[16];
    {
        int cbase = wn * 64 + tq * 2;
        #pragma unroll
        for (int ni = 0; ni < 8; ni++) {
            int n = cbase + ni * 8;
            wv[2 * ni]     = w_w[n];
            wv[2 * ni + 1] = w_w[n + 1];
            dv[2 * ni]     = g_dec[b * HID_ + n];
            dv[2 * ni + 1] = g_dec[b * HID_ + n + 1];
        }
    }
    #pragma unroll
    for (int mi = 0; mi < 2; mi++) {
        #pragma unroll
        for (int h2 = 0; h2 < 2; h2++) {
            float p = 0.f;
            #pragma unroll
            for (int ni = 0; ni < 8; ni++) {
                #pragma unroll
                for (int j = 0; j < 2; j++) {
                    float s = acc[mi][ni][h2 * 2 + j] + dv[2 * ni + j];
                    p += wv[2 * ni + j] * tanhf(s);
                }
            }
            p += __shfl_xor_sync(0xffffffffu, p, 1);
            p += __shfl_xor_sync(0xffffffffu, p, 2);
            if (tq == 0) {
                int row = wm * 32 + mi * 16 + h2 * 8 + g;
                red[row * 4 + wn] = p;
            }
        }
    }
    __syncthreads();
    if (tid < 128) {
        g_energy[m0 + tid] = red[tid * 4] + red[tid * 4 + 1]
                           + red[tid * 4 + 2] + red[tid * 4 + 3];
    }
}

// ---------------- masked softmax over T (also zeroes att_c region of out) ----------------
__global__ void softmax_kernel(const int* __restrict__ text_len, float* __restrict__ out) {
    __shared__ float sh[T_];
    __shared__ float rbuf[256];
    int b = blockIdx.x, tid = threadIdx.x;
    int len = text_len[b];

    // zero this batch's att_c slot (attc_part accumulates into it with atomics)
    ((float2*)(out + b * ENC_))[tid] = make_float2(0.f, 0.f);

    float mx = -INFINITY;
    for (int t = tid; t < len; t += 256) {
        float v = g_energy[b * T_ + t];
        sh[t] = v;
        mx = fmaxf(mx, v);
    }
    rbuf[tid] = mx; __syncthreads();
    for (int s = 128; s > 0; s >>= 1) {
        if (tid < s) rbuf[tid] = fmaxf(rbuf[tid], rbuf[tid + s]);
        __syncthreads();
    }
    mx = rbuf[0];
    __syncthreads();

    float sum = 0.f;
    for (int t = tid; t < len; t += 256) {
        float e = __expf(sh[t] - mx);
        sh[t] = e;
        sum += e;
    }
    rbuf[tid] = sum; __syncthreads();
    for (int s = 128; s > 0; s >>= 1) {
        if (tid < s) rbuf[tid] += rbuf[tid + s];
        __syncthreads();
    }
    float inv = 1.f / rbuf[0];

    float* attw = out + B_ * ENC_;
    for (int t = tid; t < len; t += 256)
        attw[b * T_ + t] = sh[t] * inv;
    for (int t = len + tid - (len & 255) + ((tid >= (len & 255)) ? 0 : 256);
         t < T_; t += 256)
        attw[b * T_ + t] = 0.f;
}

// ---------------- att_c: 32 t-slices of 64, masked skip, atomic accumulate ----------------
__global__ void attc_part(const float* __restrict__ enc, const float* __restrict__ attw,
                          const int* __restrict__ text_len, float* __restrict__ out) {
    __shared__ float w[64];
    int ts = blockIdx.x;    // 0..31
    int b  = blockIdx.y;
    int tid = threadIdx.x;  // 128

    // Slices fully beyond text_len have zero attention weight: no contribution.
    if (ts * 64 >= text_len[b]) return;

    if (tid < 64) w[tid] = attw[b * T_ + ts * 64 + tid];
    __syncthreads();

    const float4* e4 = (const float4*)(enc + ((size_t)b * T_ + ts * 64) * ENC_) + tid;
    float ax = 0.f, ay = 0.f, az = 0.f, aw = 0.f;
    #pragma unroll 8
    for (int tt = 0; tt < 64; tt++) {
        float4 v = e4[(size_t)tt * (ENC_ / 4)];
        float ww = w[tt];
        ax += ww * v.x; ay += ww * v.y; az += ww * v.z; aw += ww * v.w;
    }
    float* dst = out + b * ENC_ + tid * 4;
    atomicAdd(dst,     ax);
    atomicAdd(dst + 1, ay);
    atomicAdd(dst + 2, az);
    atomicAdd(dst + 3, aw);
}

// ---------------- launch ----------------
extern "C" void kernel_launch(void* const* d_in, const int* in_sizes, int n_in,
                              void* d_out, int out_size) {
    const float* enc       = (const float*)d_in[0];
    const float* dec_state = (const float*)d_in[1];
    const float* prev      = (const float*)d_in[2];
    const int*   text_len  = (const int*)d_in[3];
    const float* W_enc     = (const float*)d_in[4];
    const float* b_enc     = (const float*)d_in[5];
    const float* W_dec     = (const float*)d_in[6];
    const float* W_att     = (const float*)d_in[7];
    const float* conv_w    = (const float*)d_in[8];
    const float* w_w       = (const float*)d_in[9];
    // d_in[10] = w_b: additive constant cancels in softmax.
    float* out = (float*)d_out;

    cudaFuncSetAttribute(energy_kernel, cudaFuncAttributeMaxDynamicSharedMemorySize, ESMEM);

    prep_all<<<800, 256>>>(W_enc, W_att, conv_w, dec_state, W_dec, b_enc);

    energy_kernel<<<B_ * T_ / 128, 512, ESMEM>>>(enc, prev, w_w, text_len);

    softmax_kernel<<<B_, 256>>>(text_len, out);

    attc_part<<<dim3(NSLICE, B_), 128>>>(enc, out + B_ * ENC_, text_len, out);
}